// round 10
// baseline (speedup 1.0000x reference)
#include <cuda_runtime.h>
#include <cuda_bf16.h>
#include <cstdint>

// ============================================================================
// BitLinear: y = (int8(x) @ ternary(W)^T) * (w_scale * a_scale / 127)
// Exact int8 IMMA (mma.sync m16n8k32 s8) GEMM, M=32768 N=1024 K=1024.
// Base sm_100 target: cp.async + mma.sync + ldmatrix.  No tcgen05/TMA.
// R10: GEMM occupancy fix — CTA tile 128x64 (warp tile 64x16), acc regs
//      64->32, __launch_bounds__(256,3) => 3 CTAs/SM, 24 warps (was 16).
//      ncu R9: tensor pipe only 46% busy at occ 23.9% (reg-limited).
// ============================================================================

#define EPS_F 1e-8f

static constexpr int M_TOT = 32768;
static constexpr int N_TOT = 1024;
static constexpr int K_TOT = 1024;

static constexpr int BM = 128, BN = 64, BK = 64;
static constexpr int STAGES = 4;
static constexpr int KTILES = K_TOT / BK;            // 16
static constexpr int PITCH = 80;                     // 64B row padded to 80B
static constexpr int A_SM_BYTES = BM * PITCH;        // 10240
static constexpr int B_SM_BYTES = BN * PITCH;        // 5120
static constexpr int B_OFF = A_SM_BYTES;
static constexpr int STAGE_BYTES = A_SM_BYTES + B_SM_BYTES;   // 15360
static constexpr int SMEM_BYTES = STAGES * STAGE_BYTES;       // 61440

// -------------------- device scratch (static; no allocations) ---------------
__device__ int8_t g_aq[(size_t)M_TOT * K_TOT];   // 32 MB
__device__ int8_t g_wq[(size_t)N_TOT * K_TOT];   // 1 MB
__device__ float g_ascale[M_TOT];
__device__ float g_partial[1024];
__device__ float g_wscale;

// -------------------- PTX helpers -------------------------------------------
__device__ __forceinline__ uint32_t smem_u32(const void* p) {
    uint32_t a;
    asm("{ .reg .u64 t; cvta.to.shared.u64 t, %1; cvt.u32.u64 %0, t; }"
        : "=r"(a) : "l"(p));
    return a;
}

__device__ __forceinline__ void cpasync16(uint32_t dst, const void* src) {
    asm volatile("cp.async.cg.shared.global [%0], [%1], 16;"
                 :: "r"(dst), "l"(src) : "memory");
}

__device__ __forceinline__ void cp_commit() {
    asm volatile("cp.async.commit_group;" ::: "memory");
}

__device__ __forceinline__ void cp_wait2() {
    asm volatile("cp.async.wait_group 2;" ::: "memory");
}

__device__ __forceinline__ void ldsm4(uint32_t* r, uint32_t addr) {
    asm volatile("ldmatrix.sync.aligned.m8n8.x4.shared.b16 {%0,%1,%2,%3}, [%4];"
                 : "=r"(r[0]), "=r"(r[1]), "=r"(r[2]), "=r"(r[3]) : "r"(addr));
}

__device__ __forceinline__ void mma_s8(int* c, const uint32_t* a, const uint32_t* b) {
    asm volatile(
        "mma.sync.aligned.m16n8k32.row.col.s32.s8.s8.s32 "
        "{%0,%1,%2,%3}, {%4,%5,%6,%7}, {%8,%9}, {%0,%1,%2,%3};"
        : "+r"(c[0]), "+r"(c[1]), "+r"(c[2]), "+r"(c[3])
        : "r"(a[0]), "r"(a[1]), "r"(a[2]), "r"(a[3]), "r"(b[0]), "r"(b[1]));
}

// ============================================================================
// Kernel 1: per-block |W| partial sums (deterministic tree reduce)
// ============================================================================
__global__ void __launch_bounds__(256) wabs_kernel(const float* __restrict__ w) {
    __shared__ float sm[256];
    int t = threadIdx.x;
    size_t base = (size_t)blockIdx.x * 1024;
    float s = fabsf(w[base + t]) + fabsf(w[base + t + 256])
            + fabsf(w[base + t + 512]) + fabsf(w[base + t + 768]);
    sm[t] = s;
    __syncthreads();
    for (int o = 128; o > 0; o >>= 1) {
        if (t < o) sm[t] += sm[t + o];
        __syncthreads();
    }
    if (t == 0) g_partial[blockIdx.x] = sm[0];
}

// ============================================================================
// Kernel 2: ternary weight quant -> int8.  Each block re-derives w_scale
// from the 1024 partials (deterministic, identical in every block), then
// quantizes 1024 weights.  Block 0 publishes g_wscale for later kernels.
// ============================================================================
__global__ void __launch_bounds__(256) wquant_kernel(const float* __restrict__ w) {
    __shared__ float sm[256];
    int t = threadIdx.x;
    float s = g_partial[t] + g_partial[t + 256] + g_partial[t + 512] + g_partial[t + 768];
    sm[t] = s;
    __syncthreads();
    for (int o = 128; o > 0; o >>= 1) {
        if (t < o) sm[t] += sm[t + o];
        __syncthreads();
    }
    float ws = sm[0] / 1048576.0f + EPS_F;
    if (blockIdx.x == 0 && t == 0) g_wscale = ws;

    int idx = (blockIdx.x * 256 + t) * 4;
    float4 v = *(const float4*)(w + idx);
    int q0 = (int)fminf(fmaxf(rintf(v.x / ws), -1.0f), 1.0f);
    int q1 = (int)fminf(fmaxf(rintf(v.y / ws), -1.0f), 1.0f);
    int q2 = (int)fminf(fmaxf(rintf(v.z / ws), -1.0f), 1.0f);
    int q3 = (int)fminf(fmaxf(rintf(v.w / ws), -1.0f), 1.0f);
    uint32_t p = (uint32_t)(q0 & 0xFF) | ((uint32_t)(q1 & 0xFF) << 8)
               | ((uint32_t)(q2 & 0xFF) << 16) | ((uint32_t)(q3 & 0xFF) << 24);
    *(uint32_t*)(g_wq + idx) = p;
}

// ============================================================================
// Kernel 3: per-row activation quant -> int8.
// 128 threads per row (2 rows per 256-thread block).  __ldcs: x read-once.
// ============================================================================
__global__ void __launch_bounds__(256) xquant_kernel(const float* __restrict__ x) {
    __shared__ float red[8];
    int tid = threadIdx.x;
    int half = tid >> 7;
    int r = tid & 127;
    int row = blockIdx.x * 2 + half;
    const float4* xr = (const float4*)(x + (size_t)row * 1024);

    float4 v0 = __ldcs(xr + r);
    float4 v1 = __ldcs(xr + 128 + r);
    float m = fmaxf(fmaxf(fabsf(v0.x), fabsf(v0.y)), fmaxf(fabsf(v0.z), fabsf(v0.w)));
    m = fmaxf(m, fmaxf(fmaxf(fabsf(v1.x), fabsf(v1.y)),
                       fmaxf(fabsf(v1.z), fabsf(v1.w))));
#pragma unroll
    for (int o = 16; o; o >>= 1) m = fmaxf(m, __shfl_xor_sync(0xFFFFFFFFu, m, o));
    if ((tid & 31) == 0) red[tid >> 5] = m;
    __syncthreads();
    float mm = fmaxf(fmaxf(red[half * 4], red[half * 4 + 1]),
                     fmaxf(red[half * 4 + 2], red[half * 4 + 3]));
    float s = mm + EPS_F;
    if (r == 0) g_ascale[row] = s;

    float inv = 127.0f / s;
    uint32_t* q = (uint32_t*)(g_aq + (size_t)row * 1024);
    {
        int q0 = (int)rintf(fminf(fmaxf(v0.x * inv, -128.0f), 127.0f));
        int q1 = (int)rintf(fminf(fmaxf(v0.y * inv, -128.0f), 127.0f));
        int q2 = (int)rintf(fminf(fmaxf(v0.z * inv, -128.0f), 127.0f));
        int q3 = (int)rintf(fminf(fmaxf(v0.w * inv, -128.0f), 127.0f));
        q[r] = (uint32_t)(q0 & 0xFF) | ((uint32_t)(q1 & 0xFF) << 8)
             | ((uint32_t)(q2 & 0xFF) << 16) | ((uint32_t)(q3 & 0xFF) << 24);
    }
    {
        int q0 = (int)rintf(fminf(fmaxf(v1.x * inv, -128.0f), 127.0f));
        int q1 = (int)rintf(fminf(fmaxf(v1.y * inv, -128.0f), 127.0f));
        int q2 = (int)rintf(fminf(fmaxf(v1.z * inv, -128.0f), 127.0f));
        int q3 = (int)rintf(fminf(fmaxf(v1.w * inv, -128.0f), 127.0f));
        q[128 + r] = (uint32_t)(q0 & 0xFF) | ((uint32_t)(q1 & 0xFF) << 8)
                   | ((uint32_t)(q2 & 0xFF) << 16) | ((uint32_t)(q3 & 0xFF) << 24);
    }
}

// ============================================================================
// Kernel 4: int8 IMMA GEMM.  256 threads = 8 warps (2 m x 4 n),
// warp tile 64x16, CTA tile 128x64x64, 4-stage cp.async pipeline.
// 3 CTAs/SM (reg-capped via launch_bounds) -> 24 warps resident.
// ============================================================================
__global__ void __launch_bounds__(256, 3)
gemm_kernel(float* __restrict__ out) {
    extern __shared__ __align__(16) char smem[];
    int tid = threadIdx.x;
    int wid = tid >> 5, lane = tid & 31;
    int wm = wid >> 2, wn = wid & 3;           // 2 x 4 warp grid
    int g = lane >> 2, q = lane & 3;
    int m0 = (int)(blockIdx.x >> 4) * BM;
    int n0 = (int)(blockIdx.x & 15) * BN;

    // cp.async geometry: A rows 0..63 (+64 second half): thread t -> row t/4,
    // 16B chunk t%4.  B: 64 rows x 4 chunks = all 256 threads, one issue.
    int lrow = tid >> 2, lcol = tid & 3;
    const int8_t* asrc0 = g_aq + (size_t)(m0 + lrow) * K_TOT + lcol * 16;
    const int8_t* bsrc0 = g_wq + (size_t)(n0 + lrow) * K_TOT + lcol * 16;
    uint32_t sbase = smem_u32(smem);
    uint32_t adst0 = sbase + lrow * PITCH + lcol * 16;
    uint32_t bdst0 = sbase + B_OFF + lrow * PITCH + lcol * 16;

    // ldmatrix per-lane addresses (within stage 0)
    uint32_t a_lm = sbase
        + (uint32_t)(wm * 64 + (lane & 7) + ((lane >> 3) & 1) * 8) * PITCH
        + ((lane >> 4) & 1) * 16;
    uint32_t b_lm = sbase + B_OFF
        + (uint32_t)(wn * 16 + (lane & 7) + ((lane >> 4) & 1) * 8) * PITCH
        + ((lane >> 3) & 1) * 16;

    int acc[4][2][4];
#pragma unroll
    for (int i = 0; i < 4; i++)
#pragma unroll
        for (int j = 0; j < 2; j++)
#pragma unroll
            for (int r = 0; r < 4; r++) acc[i][j][r] = 0;

    // ---- prologue: fill first STAGES-1 stages ----
#pragma unroll
    for (int s = 0; s < STAGES - 1; s++) {
        uint32_t so = (uint32_t)s * STAGE_BYTES;
        cpasync16(adst0 + so, asrc0 + s * BK);
        cpasync16(adst0 + so + 64 * PITCH, asrc0 + (size_t)64 * K_TOT + s * BK);
        cpasync16(bdst0 + so, bsrc0 + s * BK);
        cp_commit();
    }

#pragma unroll 1
    for (int kt = 0; kt < KTILES; kt++) {
        cp_wait2();
        __syncthreads();

        int pf = kt + STAGES - 1;
        if (pf < KTILES) {
            uint32_t so = (uint32_t)(pf & (STAGES - 1)) * STAGE_BYTES;
            cpasync16(adst0 + so, asrc0 + pf * BK);
            cpasync16(adst0 + so + 64 * PITCH, asrc0 + (size_t)64 * K_TOT + pf * BK);
            cpasync16(bdst0 + so, bsrc0 + pf * BK);
        }
        cp_commit();

        uint32_t so = (uint32_t)(kt & (STAGES - 1)) * STAGE_BYTES;
        uint32_t As = a_lm + so;
        uint32_t Bs = b_lm + so;

#pragma unroll
        for (int ks = 0; ks < 2; ks++) {
            uint32_t a[4][4], b[2][2];
#pragma unroll
            for (int mb = 0; mb < 4; mb++)
                ldsm4(a[mb], As + mb * (16 * PITCH) + ks * 32);
            {
                uint32_t bp[4];
                ldsm4(bp, Bs + ks * 32);
                b[0][0] = bp[0]; b[0][1] = bp[1];
                b[1][0] = bp[2]; b[1][1] = bp[3];
            }
#pragma unroll
            for (int mb = 0; mb < 4; mb++)
#pragma unroll
                for (int nb = 0; nb < 2; nb++)
                    mma_s8(acc[mb][nb], a[mb], b[nb]);
        }
    }

    // ---- epilogue: dequant rescale + float2 stores ----
    float wsc = g_wscale * (1.0f / 127.0f);
#pragma unroll
    for (int mb = 0; mb < 4; mb++) {
        int r0 = m0 + wm * 64 + mb * 16 + g;
        float sc0 = wsc * g_ascale[r0];
        float sc1 = wsc * g_ascale[r0 + 8];
        float* o0 = out + (size_t)r0 * N_TOT + n0 + wn * 16 + q * 2;
        float* o1 = o0 + (size_t)8 * N_TOT;
#pragma unroll
        for (int nb = 0; nb < 2; nb++) {
            float2 v0, v1;
            v0.x = (float)acc[mb][nb][0] * sc0;
            v0.y = (float)acc[mb][nb][1] * sc0;
            v1.x = (float)acc[mb][nb][2] * sc1;
            v1.y = (float)acc[mb][nb][3] * sc1;
            *(float2*)(o0 + nb * 8) = v0;
            *(float2*)(o1 + nb * 8) = v1;
        }
    }
}

// ============================================================================
// Host launch
// ============================================================================
extern "C" void kernel_launch(void* const* d_in, const int* in_sizes, int n_in,
                              void* d_out, int out_size) {
    (void)in_sizes; (void)n_in; (void)out_size;
    const float* x = (const float*)d_in[0];
    const float* w = (const float*)d_in[1];
    float* out = (float*)d_out;

    cudaFuncSetAttribute(gemm_kernel, cudaFuncAttributeMaxDynamicSharedMemorySize,
                         SMEM_BYTES);

    wabs_kernel<<<1024, 256>>>(w);
    wquant_kernel<<<1024, 256>>>(w);
    xquant_kernel<<<M_TOT / 2, 256>>>(x);
    gemm_kernel<<<(M_TOT / BM) * (N_TOT / BN), 256, SMEM_BYTES>>>(out);
}

// round 11
// speedup vs baseline: 1.3265x; 1.3265x over previous
#include <cuda_runtime.h>
#include <cuda_bf16.h>
#include <cstdint>

// ============================================================================
// BitLinear: y = (int8(x) @ ternary(W)^T) * (w_scale * a_scale / 127)
// Exact int8 IMMA (mma.sync m16n8k32 s8) GEMM, M=32768 N=1024 K=1024.
// Base sm_100 target: cp.async + mma.sync + ldmatrix.  No tcgen05/TMA.
// R11: L1/smem-bandwidth fix — B never touches smem.  wquant emits B in
//      per-lane mma fragment order (1 MB, L2-resident); GEMM reads B
//      fragments as coalesced LDG.64.  Smem traffic/CTA-ktile 80KB->40KB.
//      Geometry = R9 (best measured: 128x128x64, warp 64x32, 2 CTA/SM).
// ============================================================================

#define EPS_F 1e-8f

static constexpr int M_TOT = 32768;
static constexpr int N_TOT = 1024;
static constexpr int K_TOT = 1024;

static constexpr int BM = 128, BN = 128, BK = 64;
static constexpr int STAGES = 4;
static constexpr int KTILES = K_TOT / BK;            // 16
static constexpr int PITCH = 80;                     // 64B row padded to 80B
static constexpr int A_SM_BYTES = BM * PITCH;        // 10240
static constexpr int STAGE_BYTES = A_SM_BYTES;       // A only
static constexpr int SMEM_BYTES = STAGES * STAGE_BYTES; // 40960

// -------------------- device scratch (static; no allocations) ---------------
__device__ int8_t g_aq[(size_t)M_TOT * K_TOT];     // 32 MB
// B in mma-fragment order: [ngrp(128)][kt(16)][ks(2)] -> 32 lanes x uint2.
// lane l holds B[ngrp*8 + l/4][kt*64 + ks*32 + (l%4)*4 + {0..3}] in .x
// and the same +16 bytes in .y  (exactly the m16n8k32 s8 B fragment).
__device__ uint2 g_bfrag[128 * 16 * 2 * 32];        // 1 MB
__device__ float g_ascale[M_TOT];
__device__ float g_partial[1024];
__device__ float g_wscale;

// -------------------- PTX helpers -------------------------------------------
__device__ __forceinline__ uint32_t smem_u32(const void* p) {
    uint32_t a;
    asm("{ .reg .u64 t; cvta.to.shared.u64 t, %1; cvt.u32.u64 %0, t; }"
        : "=r"(a) : "l"(p));
    return a;
}

__device__ __forceinline__ void cpasync16(uint32_t dst, const void* src) {
    asm volatile("cp.async.cg.shared.global [%0], [%1], 16;"
                 :: "r"(dst), "l"(src) : "memory");
}

__device__ __forceinline__ void cp_commit() {
    asm volatile("cp.async.commit_group;" ::: "memory");
}

__device__ __forceinline__ void cp_wait2() {
    asm volatile("cp.async.wait_group 2;" ::: "memory");
}

__device__ __forceinline__ void ldsm4(uint32_t* r, uint32_t addr) {
    asm volatile("ldmatrix.sync.aligned.m8n8.x4.shared.b16 {%0,%1,%2,%3}, [%4];"
                 : "=r"(r[0]), "=r"(r[1]), "=r"(r[2]), "=r"(r[3]) : "r"(addr));
}

__device__ __forceinline__ void mma_s8(int* c, const uint32_t* a,
                                       uint32_t b0, uint32_t b1) {
    asm volatile(
        "mma.sync.aligned.m16n8k32.row.col.s32.s8.s8.s32 "
        "{%0,%1,%2,%3}, {%4,%5,%6,%7}, {%8,%9}, {%0,%1,%2,%3};"
        : "+r"(c[0]), "+r"(c[1]), "+r"(c[2]), "+r"(c[3])
        : "r"(a[0]), "r"(a[1]), "r"(a[2]), "r"(a[3]), "r"(b0), "r"(b1));
}

// ============================================================================
// Kernel 1: per-block |W| partial sums (deterministic tree reduce)
// ============================================================================
__global__ void __launch_bounds__(256) wabs_kernel(const float* __restrict__ w) {
    __shared__ float sm[256];
    int t = threadIdx.x;
    size_t base = (size_t)blockIdx.x * 1024;
    float s = fabsf(w[base + t]) + fabsf(w[base + t + 256])
            + fabsf(w[base + t + 512]) + fabsf(w[base + t + 768]);
    sm[t] = s;
    __syncthreads();
    for (int o = 128; o > 0; o >>= 1) {
        if (t < o) sm[t] += sm[t + o];
        __syncthreads();
    }
    if (t == 0) g_partial[blockIdx.x] = sm[0];
}

// ============================================================================
// Kernel 2: ternary weight quant -> B fragments.  Each block re-derives
// w_scale from the 1024 partials (deterministic), quantizes 4 weights per
// thread, and scatters the packed u32 into g_bfrag in mma fragment order.
// ============================================================================
__global__ void __launch_bounds__(256) wquant_kernel(const float* __restrict__ w) {
    __shared__ float sm[256];
    int t = threadIdx.x;
    float s = g_partial[t] + g_partial[t + 256] + g_partial[t + 512] + g_partial[t + 768];
    sm[t] = s;
    __syncthreads();
    for (int o = 128; o > 0; o >>= 1) {
        if (t < o) sm[t] += sm[t + o];
        __syncthreads();
    }
    float ws = sm[0] / 1048576.0f + EPS_F;
    if (blockIdx.x == 0 && t == 0) g_wscale = ws;

    int idx = (blockIdx.x * 256 + t) * 4;          // element index into W[n][k]
    float4 v = *(const float4*)(w + idx);
    int q0 = (int)fminf(fmaxf(rintf(v.x / ws), -1.0f), 1.0f);
    int q1 = (int)fminf(fmaxf(rintf(v.y / ws), -1.0f), 1.0f);
    int q2 = (int)fminf(fmaxf(rintf(v.z / ws), -1.0f), 1.0f);
    int q3 = (int)fminf(fmaxf(rintf(v.w / ws), -1.0f), 1.0f);
    uint32_t p = (uint32_t)(q0 & 0xFF) | ((uint32_t)(q1 & 0xFF) << 8)
               | ((uint32_t)(q2 & 0xFF) << 16) | ((uint32_t)(q3 & 0xFF) << 24);

    int r = idx >> 10;                 // n row
    int k = idx & 1023;                // k of first element (aligned to 4)
    int kt = k >> 6;
    int ks = (k >> 5) & 1;
    int j  = (k >> 4) & 1;             // 0: bytes q*4, 1: +16
    int q  = (k >> 2) & 3;
    int lane = ((r & 7) << 2) | q;
    int ngrp = r >> 3;
    uint32_t* dst = (uint32_t*)&g_bfrag[((((ngrp * 16 + kt) * 2) + ks) << 5) + lane];
    dst[j] = p;
}

// ============================================================================
// Kernel 3: per-row activation quant -> int8.
// 128 threads per row (2 rows per 256-thread block).  __ldcs: x read-once.
// ============================================================================
__global__ void __launch_bounds__(256) xquant_kernel(const float* __restrict__ x) {
    __shared__ float red[8];
    int tid = threadIdx.x;
    int half = tid >> 7;
    int r = tid & 127;
    int row = blockIdx.x * 2 + half;
    const float4* xr = (const float4*)(x + (size_t)row * 1024);

    float4 v0 = __ldcs(xr + r);
    float4 v1 = __ldcs(xr + 128 + r);
    float m = fmaxf(fmaxf(fabsf(v0.x), fabsf(v0.y)), fmaxf(fabsf(v0.z), fabsf(v0.w)));
    m = fmaxf(m, fmaxf(fmaxf(fabsf(v1.x), fabsf(v1.y)),
                       fmaxf(fabsf(v1.z), fabsf(v1.w))));
#pragma unroll
    for (int o = 16; o; o >>= 1) m = fmaxf(m, __shfl_xor_sync(0xFFFFFFFFu, m, o));
    if ((tid & 31) == 0) red[tid >> 5] = m;
    __syncthreads();
    float mm = fmaxf(fmaxf(red[half * 4], red[half * 4 + 1]),
                     fmaxf(red[half * 4 + 2], red[half * 4 + 3]));
    float s = mm + EPS_F;
    if (r == 0) g_ascale[row] = s;

    float inv = 127.0f / s;
    uint32_t* q = (uint32_t*)(g_aq + (size_t)row * 1024);
    {
        int q0 = (int)rintf(fminf(fmaxf(v0.x * inv, -128.0f), 127.0f));
        int q1 = (int)rintf(fminf(fmaxf(v0.y * inv, -128.0f), 127.0f));
        int q2 = (int)rintf(fminf(fmaxf(v0.z * inv, -128.0f), 127.0f));
        int q3 = (int)rintf(fminf(fmaxf(v0.w * inv, -128.0f), 127.0f));
        q[r] = (uint32_t)(q0 & 0xFF) | ((uint32_t)(q1 & 0xFF) << 8)
             | ((uint32_t)(q2 & 0xFF) << 16) | ((uint32_t)(q3 & 0xFF) << 24);
    }
    {
        int q0 = (int)rintf(fminf(fmaxf(v1.x * inv, -128.0f), 127.0f));
        int q1 = (int)rintf(fminf(fmaxf(v1.y * inv, -128.0f), 127.0f));
        int q2 = (int)rintf(fminf(fmaxf(v1.z * inv, -128.0f), 127.0f));
        int q3 = (int)rintf(fminf(fmaxf(v1.w * inv, -128.0f), 127.0f));
        q[128 + r] = (uint32_t)(q0 & 0xFF) | ((uint32_t)(q1 & 0xFF) << 8)
                   | ((uint32_t)(q2 & 0xFF) << 16) | ((uint32_t)(q3 & 0xFF) << 24);
    }
}

// ============================================================================
// Kernel 4: int8 IMMA GEMM.  256 threads = 8 warps (2 m x 4 n),
// warp tile 64x32, CTA tile 128x128x64.  A: 4-stage cp.async + ldmatrix.
// B: direct coalesced LDG.64 of precomputed fragments (L2-resident, no smem).
// ============================================================================
__global__ void __launch_bounds__(256, 2)
gemm_kernel(float* __restrict__ out) {
    extern __shared__ __align__(16) char smem[];
    int tid = threadIdx.x;
    int wid = tid >> 5, lane = tid & 31;
    int wm = wid >> 2, wn = wid & 3;           // 2 x 4 warp grid
    int g = lane >> 2, q = lane & 3;
    int m0 = (int)(blockIdx.x >> 3) * BM;
    int n0 = (int)(blockIdx.x & 7) * BN;

    // A cp.async geometry: thread t -> row t/4, 16B chunk t%4 (x2 halves)
    int lrow = tid >> 2, lcol = tid & 3;
    const int8_t* asrc0 = g_aq + (size_t)(m0 + lrow) * K_TOT + lcol * 16;
    uint32_t sbase = smem_u32(smem);
    uint32_t adst0 = sbase + lrow * PITCH + lcol * 16;

    // A ldmatrix per-lane address (within stage 0)
    uint32_t a_lm = sbase
        + (uint32_t)(wm * 64 + (lane & 7) + ((lane >> 3) & 1) * 8) * PITCH
        + ((lane >> 4) & 1) * 16;

    // B fragment pointer: warp covers n-groups (n0/8 + wn*4) .. +3.
    // ngrp stride in uint2 = 16*2*32 = 1024.
    const uint2* bwp = g_bfrag + (size_t)((n0 >> 3) + wn * 4) * 1024 + lane;

    int acc[4][4][4];
#pragma unroll
    for (int i = 0; i < 4; i++)
#pragma unroll
        for (int j = 0; j < 4; j++)
#pragma unroll
            for (int r = 0; r < 4; r++) acc[i][j][r] = 0;

    // ---- prologue: fill first STAGES-1 stages (A only) ----
#pragma unroll
    for (int s = 0; s < STAGES - 1; s++) {
        uint32_t so = (uint32_t)s * STAGE_BYTES;
        cpasync16(adst0 + so, asrc0 + s * BK);
        cpasync16(adst0 + so + 64 * PITCH, asrc0 + (size_t)64 * K_TOT + s * BK);
        cp_commit();
    }

#pragma unroll 1
    for (int kt = 0; kt < KTILES; kt++) {
        // B fragment loads for this k-tile: issued BEFORE the pipeline wait
        // so their L2 latency hides behind it.  bv[nb*2+ks].
        uint2 bv[8];
#pragma unroll
        for (int nb = 0; nb < 4; nb++) {
            bv[nb * 2 + 0] = __ldg(bwp + nb * 1024 + kt * 64);
            bv[nb * 2 + 1] = __ldg(bwp + nb * 1024 + kt * 64 + 32);
        }

        cp_wait2();
        __syncthreads();

        int pf = kt + STAGES - 1;
        if (pf < KTILES) {
            uint32_t so = (uint32_t)(pf & (STAGES - 1)) * STAGE_BYTES;
            cpasync16(adst0 + so, asrc0 + pf * BK);
            cpasync16(adst0 + so + 64 * PITCH, asrc0 + (size_t)64 * K_TOT + pf * BK);
        }
        cp_commit();

        uint32_t As = a_lm + (uint32_t)(kt & (STAGES - 1)) * STAGE_BYTES;

#pragma unroll
        for (int ks = 0; ks < 2; ks++) {
            uint32_t a[4][4];
#pragma unroll
            for (int mb = 0; mb < 4; mb++)
                ldsm4(a[mb], As + mb * (16 * PITCH) + ks * 32);
#pragma unroll
            for (int mb = 0; mb < 4; mb++)
#pragma unroll
                for (int nb = 0; nb < 4; nb++)
                    mma_s8(acc[mb][nb], a[mb],
                           bv[nb * 2 + ks].x, bv[nb * 2 + ks].y);
        }
    }

    // ---- epilogue: dequant rescale + float2 stores ----
    float wsc = g_wscale * (1.0f / 127.0f);
#pragma unroll
    for (int mb = 0; mb < 4; mb++) {
        int r0 = m0 + wm * 64 + mb * 16 + g;
        float sc0 = wsc * g_ascale[r0];
        float sc1 = wsc * g_ascale[r0 + 8];
        float* o0 = out + (size_t)r0 * N_TOT + n0 + wn * 32 + q * 2;
        float* o1 = o0 + (size_t)8 * N_TOT;
#pragma unroll
        for (int nb = 0; nb < 4; nb++) {
            float2 v0, v1;
            v0.x = (float)acc[mb][nb][0] * sc0;
            v0.y = (float)acc[mb][nb][1] * sc0;
            v1.x = (float)acc[mb][nb][2] * sc1;
            v1.y = (float)acc[mb][nb][3] * sc1;
            *(float2*)(o0 + nb * 8) = v0;
            *(float2*)(o1 + nb * 8) = v1;
        }
    }
}

// ============================================================================
// Host launch
// ============================================================================
extern "C" void kernel_launch(void* const* d_in, const int* in_sizes, int n_in,
                              void* d_out, int out_size) {
    (void)in_sizes; (void)n_in; (void)out_size;
    const float* x = (const float*)d_in[0];
    const float* w = (const float*)d_in[1];
    float* out = (float*)d_out;

    cudaFuncSetAttribute(gemm_kernel, cudaFuncAttributeMaxDynamicSharedMemorySize,
                         SMEM_BYTES);

    wabs_kernel<<<1024, 256>>>(w);
    wquant_kernel<<<1024, 256>>>(w);
    xquant_kernel<<<M_TOT / 2, 256>>>(x);
    gemm_kernel<<<(M_TOT / BM) * (N_TOT / BN), 256, SMEM_BYTES>>>(out);
}